// round 6
// baseline (speedup 1.0000x reference)
#include <cuda_runtime.h>
#include <cuda_fp16.h>

#define V 8192
#define E 262144
#define D 128
#define SLOTS 128           // hash slots per row (power of 2, >= ~2x max degree)
#define GB 256              // gemm grid (V / 32 rows per block)

// dynamic smem layout for k_gemm (floats): W[128][132] + A[128][34] + 192
#define SW_STRIDE 132
#define SA_STRIDE 34
#define GEMM_SMEM_FLOATS (128 * SW_STRIDE + 128 * SA_STRIDE + 192)
#define GEMM_SMEM_BYTES  (GEMM_SMEM_FLOATS * 4)

// ---------------- scratch (device globals; no allocations allowed) ----------
__device__ __half             g_hwh[V * D];        // h @ W^T in fp16 (2 MB)
__device__ float              g_s1[V];             // hw[v] . att[:128]
__device__ float              g_s2[V];             // hw[v] . att[128:]
__device__ float              g_Spart[GB * D];     // per-gemm-block colsum partials
__device__ float              g_S[D];              // reduced colsum
__device__ unsigned long long g_ew64[(size_t)V * SLOTS];  // hash: (idx+1)<<29|dst<<16|half(w)
__device__ int                g_is64;              // edge_index dtype flag

// =================== K1: GEMM hw = h @ W^T (W resident in smem) ==============
// 32 rows x 128 cols per block, 256 threads (tx 0..15 cols, ty 0..15 rows),
// each thread 2 rows x 8 cols. Full W (64KB, [k][col]) + A tile ([k][row]) in
// dynamic smem; k-loop has NO barriers. Epilogue: fp16 hw, s1/s2, colsum part.
__global__ void __launch_bounds__(256) k_gemm(const float* __restrict__ h,
                                              const float* __restrict__ Wm,
                                              const float* __restrict__ att,
                                              const int* __restrict__ e32) {
    extern __shared__ float smem[];
    float* sW  = smem;                        // [k][col], stride 132
    float* sA  = smem + 128 * SW_STRIDE;      // [k][row], stride 34
    float* s1s = sA + 128 * SA_STRIDE;        // 32
    float* s2s = s1s + 32;                    // 32
    float* cs  = s2s + 32;                    // 128

    int tid = threadIdx.x;
    int tx = tid & 15, ty = tid >> 4;
    int row0 = blockIdx.x * 32;

    // int64/int32 detection (block 0): int64 values < 2^13 => odd words all 0
    if (blockIdx.x == 0) {
        __shared__ int flag;
        if (tid == 0) flag = 0;
        __syncthreads();
        if (e32[2 * tid + 1] != 0) atomicExch(&flag, 1);
        __syncthreads();
        if (tid == 0) g_is64 = (flag == 0) ? 1 : 0;
    }

    if (tid < 32) { s1s[tid] = 0.f; s2s[tid] = 0.f; }
    if (tid < 128) cs[tid] = 0.f;

    // ---- load W (128x128) transposed into sW[k][col]: 4096 float4, 16/thread
#pragma unroll
    for (int i = 0; i < 16; i++) {
        int idx = tid + i * 256;
        int col = idx >> 5, q = idx & 31;
        float4 v = *(const float4*)(Wm + (size_t)col * D + q * 4);
        sW[(q * 4 + 0) * SW_STRIDE + col] = v.x;
        sW[(q * 4 + 1) * SW_STRIDE + col] = v.y;
        sW[(q * 4 + 2) * SW_STRIDE + col] = v.z;
        sW[(q * 4 + 3) * SW_STRIDE + col] = v.w;
    }
    // ---- load A (32x128) transposed into sA[k][row]: 1024 float4, 4/thread
#pragma unroll
    for (int i = 0; i < 4; i++) {
        int idx = tid + i * 256;
        int row = idx >> 5, q = idx & 31;
        float4 v = *(const float4*)(h + (size_t)(row0 + row) * D + q * 4);
        sA[(q * 4 + 0) * SA_STRIDE + row] = v.x;
        sA[(q * 4 + 1) * SA_STRIDE + row] = v.y;
        sA[(q * 4 + 2) * SA_STRIDE + row] = v.z;
        sA[(q * 4 + 3) * SA_STRIDE + row] = v.w;
    }
    __syncthreads();

    // ---- barrier-free mainloop over k = 0..127
    float acc[2][8];
#pragma unroll
    for (int r = 0; r < 2; r++)
#pragma unroll
        for (int c = 0; c < 8; c++) acc[r][c] = 0.f;

#pragma unroll 8
    for (int k = 0; k < 128; k++) {
        float a0 = sA[k * SA_STRIDE + ty * 2 + 0];
        float a1 = sA[k * SA_STRIDE + ty * 2 + 1];
        float4 b0 = *(const float4*)&sW[k * SW_STRIDE + tx * 8];
        float4 b1 = *(const float4*)&sW[k * SW_STRIDE + tx * 8 + 4];
        float bv[8] = {b0.x, b0.y, b0.z, b0.w, b1.x, b1.y, b1.z, b1.w};
#pragma unroll
        for (int c = 0; c < 8; c++) {
            acc[0][c] += a0 * bv[c];
            acc[1][c] += a1 * bv[c];
        }
    }

    // ---- epilogue ----
#pragma unroll
    for (int r = 0; r < 2; r++) {
        int row = row0 + ty * 2 + r;
        __half2 h0 = __floats2half2_rn(acc[r][0], acc[r][1]);
        __half2 h1 = __floats2half2_rn(acc[r][2], acc[r][3]);
        __half2 h2 = __floats2half2_rn(acc[r][4], acc[r][5]);
        __half2 h3 = __floats2half2_rn(acc[r][6], acc[r][7]);
        uint4 u;
        u.x = *(unsigned*)&h0; u.y = *(unsigned*)&h1;
        u.z = *(unsigned*)&h2; u.w = *(unsigned*)&h3;
        *(uint4*)((__half*)g_hwh + (size_t)row * D + tx * 8) = u;
    }

    float4 A1a = *(const float4*)(att + tx * 8);
    float4 A1b = *(const float4*)(att + tx * 8 + 4);
    float4 A2a = *(const float4*)(att + D + tx * 8);
    float4 A2b = *(const float4*)(att + D + tx * 8 + 4);
    float a1v[8] = {A1a.x, A1a.y, A1a.z, A1a.w, A1b.x, A1b.y, A1b.z, A1b.w};
    float a2v[8] = {A2a.x, A2a.y, A2a.z, A2a.w, A2b.x, A2b.y, A2b.z, A2b.w};
#pragma unroll
    for (int r = 0; r < 2; r++) {
        float p1 = 0.f, p2 = 0.f;
#pragma unroll
        for (int c = 0; c < 8; c++) { p1 += acc[r][c] * a1v[c]; p2 += acc[r][c] * a2v[c]; }
        atomicAdd(&s1s[ty * 2 + r], p1);
        atomicAdd(&s2s[ty * 2 + r], p2);
    }
#pragma unroll
    for (int c = 0; c < 8; c++)
        atomicAdd(&cs[tx * 8 + c], acc[0][c] + acc[1][c]);
    __syncthreads();
    if (tid < 32) { g_s1[row0 + tid] = s1s[tid]; g_s2[row0 + tid] = s2s[tid]; }
    if (tid < 128) g_Spart[blockIdx.x * D + tid] = cs[tid];   // race-free partial
}

// =================== K2: per-edge logit + hash insert (dedup by atomicMax) ===
// Record: bits[0:16)=half(w), [16:29)=dst, [29:48)=edge_idx+1  (max idx wins)
__global__ void k_scatter(const int* __restrict__ e32) {
    // block 0 additionally reduces colsum partials -> g_S (k_row runs later)
    if (blockIdx.x == 0 && threadIdx.x < 128) {
        float s = 0.f;
#pragma unroll 8
        for (int b = 0; b < GB; b++) s += g_Spart[b * D + threadIdx.x];
        g_S[threadIdx.x] = s;
    }
    int e = blockIdx.x * blockDim.x + threadIdx.x;
    if (e >= E) return;
    int src, dst;
    if (g_is64) {
        src = ((const int2*)e32)[e].x;
        dst = ((const int2*)e32)[E + e].x;
    } else {
        src = e32[e];
        dst = e32[E + e];
    }
    float a = g_s1[src] + g_s2[dst];
    a = a > 0.f ? a : 0.2f * a;                       // LeakyReLU(0.2)
    float w = expm1f(a);                              // exp(a) - 1
    unsigned wh = (unsigned)__half_as_ushort(__float2half_rn(w));
    unsigned long long rec = ((unsigned long long)(unsigned)(e + 1) << 29)
                           | ((unsigned long long)(unsigned)dst << 16) | wh;
    unsigned slot = ((unsigned)dst * 2654435761u) >> 25;   // 7-bit hash
    unsigned long long* tab = g_ew64 + (size_t)src * SLOTS;
    for (int probe = 0; probe < SLOTS; probe++) {
        unsigned long long old = atomicCAS(&tab[slot], 0ULL, rec);
        if (old == 0ULL) break;                            // claimed empty slot
        if (((unsigned)(old >> 16) & 0x1FFFu) == (unsigned)dst) {
            atomicMax(&tab[slot], rec);                    // last-write-wins
            break;
        }
        slot = (slot + 1) & (SLOTS - 1);
    }
}

// =================== K3: slot scan + compact + gather + normalize ============
__global__ void __launch_bounds__(256, 5) k_row(float* __restrict__ out) {
    __shared__ uint2 sm[8][SLOTS];     // {dst, float bits of w}
    int wid = threadIdx.x >> 5, lane = threadIdx.x & 31;
    int row = blockIdx.x * 8 + wid;
    unsigned long long* tab = g_ew64 + (size_t)row * SLOTS;

    float dsum = 0.f;
    int cnt = 0;
#pragma unroll
    for (int rnd = 0; rnd < SLOTS / 32; rnd++) {
        int s = rnd * 32 + lane;
        unsigned long long v = tab[s];
        tab[s] = 0ULL;                                   // replay-safe re-zero
        unsigned mask = __ballot_sync(0xffffffffu, v != 0ULL);
        if (v != 0ULL) {
            int pos = cnt + __popc(mask & ((1u << lane) - 1u));
            float w = __half2float(__ushort_as_half((unsigned short)(v & 0xFFFFu)));
            sm[wid][pos] = make_uint2((unsigned)(v >> 16) & 0x1FFFu,
                                      __float_as_uint(w));
            dsum += w;
        }
        cnt += __popc(mask);
    }
    int dpad = (cnt + 7) & ~7;
    for (int t = cnt + lane; t < dpad; t += 32)
        sm[wid][t] = make_uint2(0u, 0u);                 // harmless pad (w=0)
    __syncwarp();

    // pair-gather: lanes 0-15 edge A, 16-31 edge B; 16B (8 halves) per lane
    float acc[8];
#pragma unroll
    for (int i = 0; i < 8; i++) acc[i] = 0.f;
    int half_ = lane >> 4;
    int cl = (lane & 15) * 8;
    const __half* hw = g_hwh;

    for (int t = 0; t < dpad; t += 8) {
#pragma unroll
        for (int p = 0; p < 4; p++) {
            uint2 m = sm[wid][t + 2 * p + half_];
            float w = __uint_as_float(m.y);
            uint4 v = *(const uint4*)(hw + (size_t)m.x * D + cl);
            float2 f0 = __half22float2(*(__half2*)&v.x);
            float2 f1 = __half22float2(*(__half2*)&v.y);
            float2 f2 = __half22float2(*(__half2*)&v.z);
            float2 f3 = __half22float2(*(__half2*)&v.w);
            acc[0] += w * f0.x; acc[1] += w * f0.y;
            acc[2] += w * f1.x; acc[3] += w * f1.y;
            acc[4] += w * f2.x; acc[5] += w * f2.y;
            acc[6] += w * f3.x; acc[7] += w * f3.y;
        }
    }

#pragma unroll
    for (int i = 0; i < 8; i++) acc[i] += __shfl_xor_sync(0xffffffffu, acc[i], 16);
#pragma unroll
    for (int o = 16; o; o >>= 1) dsum += __shfl_xor_sync(0xffffffffu, dsum, o);

    float inv = 1.f / ((float)V + dsum);
    if (lane < 16) {
        float4 Sa = *(const float4*)(g_S + cl);
        float4 Sb = *(const float4*)(g_S + cl + 4);
        float4 o0, o1;
        o0.x = (Sa.x + acc[0]) * inv; o0.y = (Sa.y + acc[1]) * inv;
        o0.z = (Sa.z + acc[2]) * inv; o0.w = (Sa.w + acc[3]) * inv;
        o1.x = (Sb.x + acc[4]) * inv; o1.y = (Sb.y + acc[5]) * inv;
        o1.z = (Sb.z + acc[6]) * inv; o1.w = (Sb.w + acc[7]) * inv;
        *(float4*)(out + (size_t)row * D + cl) = o0;
        *(float4*)(out + (size_t)row * D + cl + 4) = o1;
    }
}

// ----------------------------------------------------------------------------
extern "C" void kernel_launch(void* const* d_in, const int* in_sizes, int n_in,
                              void* d_out, int out_size) {
    const float* h   = (const float*)d_in[0];
    const int*   ei  = (const int*)d_in[1];
    const float* Wm  = (const float*)d_in[2];
    const float* att = (const float*)d_in[3];
    float* out = (float*)d_out;

    cudaFuncSetAttribute(k_gemm, cudaFuncAttributeMaxDynamicSharedMemorySize,
                         GEMM_SMEM_BYTES);
    k_gemm<<<GB, 256, GEMM_SMEM_BYTES>>>(h, Wm, att, ei);
    k_scatter<<<E / 256, 256>>>(ei);
    k_row<<<V / 8, 256>>>(out);
}

// round 8
// speedup vs baseline: 1.0036x; 1.0036x over previous
#include <cuda_runtime.h>
#include <cuda_fp16.h>
#include <mma.h>
using namespace nvcuda;

#define V 8192
#define E 262144
#define D 128
#define SLOTS 128           // hash slots per row (power of 2)

// ---------------- scratch (device globals; no allocations allowed) ----------
__device__ __half             g_hwh[V * D];      // hw in fp16 (2 MB, L2-resident)
__device__ __half             g_hhi[V * D];      // h split hi (2 MB)
__device__ __half             g_hlo[V * D];      // h split lo (2 MB)
__device__ __half             g_Whi[D * D];      // W split hi (32 KB)
__device__ __half             g_Wlo[D * D];      // W split lo (32 KB)
__device__ float              g_u1[D], g_u2[D];  // u1 = W^T att1, u2 = W^T att2
__device__ float              g_s1[V];           // s1[v] = h[v] . u1  (exact fp32)
__device__ float              g_s2[V];           // s2[v] = h[v] . u2
__device__ float              g_hsumpart[128 * D]; // per-block column sums of h
__device__ float              g_S[D];            // S = hsum @ W^T
__device__ unsigned long long g_ew64[(size_t)V * SLOTS]; // (idx+1)<<29|dst<<16|half(w)
__device__ int                g_is64;            // edge_index dtype flag

// =================== K0: detect dtype + split W + u1/u2 ======================
__global__ void k0(const float* __restrict__ Wm, const float* __restrict__ att,
                   const int* __restrict__ e32) {
    int t = threadIdx.x;
    __shared__ int flag;
    if (t == 0) flag = 0;
    __syncthreads();
    if (e32[2 * t + 1] != 0) atomicExch(&flag, 1);
    __syncthreads();
    if (t == 0) g_is64 = (flag == 0) ? 1 : 0;

    for (int i = t; i < D * D; i += 256) {
        float w = Wm[i];
        __half hi = __float2half_rn(w);
        g_Whi[i] = hi;
        g_Wlo[i] = __float2half_rn(w - __half2float(hi));
    }
    if (t < D) {
        float u1 = 0.f, u2 = 0.f;
        for (int c = 0; c < D; c++) {
            float w = Wm[c * D + t];
            u1 += att[c] * w;
            u2 += att[D + c] * w;
        }
        g_u1[t] = u1;
        g_u2[t] = u2;
    }
}

// =================== K1: split h + s1/s2 dots + colsum partials ==============
// grid 128 x 256 threads; each warp handles 8 rows; lane owns 4 columns.
__global__ void __launch_bounds__(256) k_prep(const float* __restrict__ h) {
    __shared__ float cs[D];
    int tid = threadIdx.x, lane = tid & 31, warp = tid >> 5;
    if (tid < D) cs[tid] = 0.f;
    __syncthreads();

    float4 u1v = *(const float4*)(g_u1 + lane * 4);
    float4 u2v = *(const float4*)(g_u2 + lane * 4);
    float c0 = 0.f, c1 = 0.f, c2 = 0.f, c3 = 0.f;
    int rbase = blockIdx.x * 64 + warp * 8;

    for (int r = 0; r < 8; r++) {
        int row = rbase + r;
        float4 hv = *(const float4*)(h + (size_t)row * D + lane * 4);
        float s1 = hv.x * u1v.x + hv.y * u1v.y + hv.z * u1v.z + hv.w * u1v.w;
        float s2 = hv.x * u2v.x + hv.y * u2v.y + hv.z * u2v.z + hv.w * u2v.w;
#pragma unroll
        for (int o = 16; o; o >>= 1) {
            s1 += __shfl_xor_sync(0xffffffffu, s1, o);
            s2 += __shfl_xor_sync(0xffffffffu, s2, o);
        }
        if (lane == 0) { g_s1[row] = s1; g_s2[row] = s2; }

        __half hx = __float2half_rn(hv.x), hy = __float2half_rn(hv.y);
        __half hz = __float2half_rn(hv.z), hwv = __float2half_rn(hv.w);
        __half lx = __float2half_rn(hv.x - __half2float(hx));
        __half ly = __float2half_rn(hv.y - __half2float(hy));
        __half lz = __float2half_rn(hv.z - __half2float(hz));
        __half lw = __float2half_rn(hv.w - __half2float(hwv));
        __half2 hp0 = __halves2half2(hx, hy), hp1 = __halves2half2(hz, hwv);
        __half2 lp0 = __halves2half2(lx, ly), lp1 = __halves2half2(lz, lw);
        uint2 uh, ul;
        uh.x = *(unsigned*)&hp0; uh.y = *(unsigned*)&hp1;
        ul.x = *(unsigned*)&lp0; ul.y = *(unsigned*)&lp1;
        *(uint2*)(g_hhi + (size_t)row * D + lane * 4) = uh;
        *(uint2*)(g_hlo + (size_t)row * D + lane * 4) = ul;

        c0 += hv.x; c1 += hv.y; c2 += hv.z; c3 += hv.w;
    }
    atomicAdd(&cs[lane * 4 + 0], c0);
    atomicAdd(&cs[lane * 4 + 1], c1);
    atomicAdd(&cs[lane * 4 + 2], c2);
    atomicAdd(&cs[lane * 4 + 3], c3);
    __syncthreads();
    if (tid < D) g_hsumpart[blockIdx.x * D + tid] = cs[tid];
}

// =================== K2: tensor-core GEMM hw = h @ W^T (fp16-split) ==========
// 1024 warp-tasks: 512 row-tiles (16 rows) x 2 col-halves (64 cols).
// Per warp: 4 accum tiles (16x16), K loop 8x16; 3 MMAs per (k, coltile).
__global__ void __launch_bounds__(128) k_gemm(void) {
    __shared__ float st[4][256];
    int warpId = threadIdx.x >> 5, lane = threadIdx.x & 31;
    int wt = blockIdx.x * 4 + warpId;
    int rt = wt >> 1, ch = wt & 1;

    wmma::fragment<wmma::accumulator, 16, 16, 16, float> acc[4];
#pragma unroll
    for (int ct = 0; ct < 4; ct++) wmma::fill_fragment(acc[ct], 0.f);

    const __half* Ahi = g_hhi + (size_t)rt * 16 * D;
    const __half* Alo = g_hlo + (size_t)rt * 16 * D;

#pragma unroll
    for (int k0 = 0; k0 < 8; k0++) {
        wmma::fragment<wmma::matrix_a, 16, 16, 16, __half, wmma::row_major> ahi, alo;
        wmma::load_matrix_sync(ahi, Ahi + k0 * 16, D);
        wmma::load_matrix_sync(alo, Alo + k0 * 16, D);
#pragma unroll
        for (int ct = 0; ct < 4; ct++) {
            // B col_major: B(k,c) = W[c][k]  ->  ptr = W + c0*D + k0*16, ldm=D
            const __half* bp_hi = g_Whi + (size_t)(ch * 64 + ct * 16) * D + k0 * 16;
            const __half* bp_lo = g_Wlo + (size_t)(ch * 64 + ct * 16) * D + k0 * 16;
            wmma::fragment<wmma::matrix_b, 16, 16, 16, __half, wmma::col_major> bhi, blo;
            wmma::load_matrix_sync(bhi, bp_hi, D);
            wmma::load_matrix_sync(blo, bp_lo, D);
            wmma::mma_sync(acc[ct], ahi, bhi, acc[ct]);
            wmma::mma_sync(acc[ct], ahi, blo, acc[ct]);
            wmma::mma_sync(acc[ct], alo, bhi, acc[ct]);
        }
    }

    // epilogue: stage each 16x16 fp32 tile in smem, convert to fp16, store
#pragma unroll
    for (int ct = 0; ct < 4; ct++) {
        wmma::store_matrix_sync(st[warpId], acc[ct], 16, wmma::mem_row_major);
        __syncwarp();
        int r = lane >> 1, cg = (lane & 1) * 8;
        const float* p = st[warpId] + r * 16 + cg;
        __half2 q0 = __floats2half2_rn(p[0], p[1]);
        __half2 q1 = __floats2half2_rn(p[2], p[3]);
        __half2 q2 = __floats2half2_rn(p[4], p[5]);
        __half2 q3 = __floats2half2_rn(p[6], p[7]);
        uint4 u;
        u.x = *(unsigned*)&q0; u.y = *(unsigned*)&q1;
        u.z = *(unsigned*)&q2; u.w = *(unsigned*)&q3;
        *(uint4*)(g_hwh + (size_t)(rt * 16 + r) * D + ch * 64 + ct * 16 + cg) = u;
        __syncwarp();
    }
}

// =================== K3: per-edge logit + hash insert (dedup by atomicMax) ===
__global__ void k_scatter(const int* __restrict__ e32, const float* __restrict__ Wm) {
    // block 0: reduce hsum partials, then S = hsum @ W^T  (k_row reads g_S later)
    if (blockIdx.x == 0) {
        __shared__ float hs[D];
        if (threadIdx.x < D) {
            float s = 0.f;
#pragma unroll 8
            for (int b = 0; b < 128; b++) s += g_hsumpart[b * D + threadIdx.x];
            hs[threadIdx.x] = s;
        }
        __syncthreads();
        if (threadIdx.x < D) {
            float S = 0.f;
            for (int k = 0; k < D; k++) S += hs[k] * Wm[threadIdx.x * D + k];
            g_S[threadIdx.x] = S;
        }
    }
    int e = blockIdx.x * blockDim.x + threadIdx.x;
    if (e >= E) return;
    int src, dst;
    if (g_is64) {
        src = ((const int2*)e32)[e].x;
        dst = ((const int2*)e32)[E + e].x;
    } else {
        src = e32[e];
        dst = e32[E + e];
    }
    float a = g_s1[src] + g_s2[dst];
    a = a > 0.f ? a : 0.2f * a;                       // LeakyReLU(0.2)
    float w = expm1f(a);                              // exp(a) - 1
    unsigned wh = (unsigned)__half_as_ushort(__float2half_rn(w));
    unsigned long long rec = ((unsigned long long)(unsigned)(e + 1) << 29)
                           | ((unsigned long long)(unsigned)dst << 16) | wh;
    unsigned slot = ((unsigned)dst * 2654435761u) >> 25;   // 7-bit hash
    unsigned long long* tab = g_ew64 + (size_t)src * SLOTS;
    for (int probe = 0; probe < SLOTS; probe++) {
        unsigned long long old = atomicCAS(&tab[slot], 0ULL, rec);
        if (old == 0ULL) break;
        if (((unsigned)(old >> 16) & 0x1FFFu) == (unsigned)dst) {
            atomicMax(&tab[slot], rec);                    // last-write-wins
            break;
        }
        slot = (slot + 1) & (SLOTS - 1);
    }
}

// =================== K4: slot scan + compact + gather + normalize ============
__global__ void __launch_bounds__(256, 5) k_row(float* __restrict__ out) {
    __shared__ uint2 sm[8][SLOTS];
    int wid = threadIdx.x >> 5, lane = threadIdx.x & 31;
    int row = blockIdx.x * 8 + wid;
    unsigned long long* tab = g_ew64 + (size_t)row * SLOTS;

    float dsum = 0.f;
    int cnt = 0;
#pragma unroll
    for (int rnd = 0; rnd < SLOTS / 32; rnd++) {
        int s = rnd * 32 + lane;
        unsigned long long v = tab[s];
        tab[s] = 0ULL;                                   // replay-safe re-zero
        unsigned mask = __ballot_sync(0xffffffffu, v != 0ULL);
        if (v != 0ULL) {
            int pos = cnt + __popc(mask & ((1u << lane) - 1u));
            float w = __half2float(__ushort_as_half((unsigned short)(v & 0xFFFFu)));
            sm[wid][pos] = make_uint2((unsigned)(v >> 16) & 0x1FFFu,
                                      __float_as_uint(w));
            dsum += w;
        }
        cnt += __popc(mask);
    }
    int dpad = (cnt + 7) & ~7;
    for (int t = cnt + lane; t < dpad; t += 32)
        sm[wid][t] = make_uint2(0u, 0u);
    __syncwarp();

    float acc[8];
#pragma unroll
    for (int i = 0; i < 8; i++) acc[i] = 0.f;
    int half_ = lane >> 4;
    int cl = (lane & 15) * 8;
    const __half* hw = g_hwh;

    for (int t = 0; t < dpad; t += 8) {
#pragma unroll
        for (int p = 0; p < 4; p++) {
            uint2 m = sm[wid][t + 2 * p + half_];
            float w = __uint_as_float(m.y);
            uint4 v = *(const uint4*)(hw + (size_t)m.x * D + cl);
            float2 f0 = __half22float2(*(__half2*)&v.x);
            float2 f1 = __half22float2(*(__half2*)&v.y);
            float2 f2 = __half22float2(*(__half2*)&v.z);
            float2 f3 = __half22float2(*(__half2*)&v.w);
            acc[0] += w * f0.x; acc[1] += w * f0.y;
            acc[2] += w * f1.x; acc[3] += w * f1.y;
            acc[4] += w * f2.x; acc[5] += w * f2.y;
            acc[6] += w * f3.x; acc[7] += w * f3.y;
        }
    }

#pragma unroll
    for (int i = 0; i < 8; i++) acc[i] += __shfl_xor_sync(0xffffffffu, acc[i], 16);
#pragma unroll
    for (int o = 16; o; o >>= 1) dsum += __shfl_xor_sync(0xffffffffu, dsum, o);

    float inv = 1.f / ((float)V + dsum);
    if (lane < 16) {
        float4 Sa = *(const float4*)(g_S + cl);
        float4 Sb = *(const float4*)(g_S + cl + 4);
        float4 o0, o1;
        o0.x = (Sa.x + acc[0]) * inv; o0.y = (Sa.y + acc[1]) * inv;
        o0.z = (Sa.z + acc[2]) * inv; o0.w = (Sa.w + acc[3]) * inv;
        o1.x = (Sb.x + acc[4]) * inv; o1.y = (Sb.y + acc[5]) * inv;
        o1.z = (Sb.z + acc[6]) * inv; o1.w = (Sb.w + acc[7]) * inv;
        *(float4*)(out + (size_t)row * D + cl) = o0;
        *(float4*)(out + (size_t)row * D + cl + 4) = o1;
    }
}

// ----------------------------------------------------------------------------
extern "C" void kernel_launch(void* const* d_in, const int* in_sizes, int n_in,
                              void* d_out, int out_size) {
    const float* h   = (const float*)d_in[0];
    const int*   ei  = (const int*)d_in[1];
    const float* Wm  = (const float*)d_in[2];
    const float* att = (const float*)d_in[3];
    float* out = (float*)d_out;

    k0<<<1, 256>>>(Wm, att, ei);
    k_prep<<<128, 256>>>(h);
    k_gemm<<<256, 128>>>();
    k_scatter<<<E / 256, 256>>>(ei, Wm);
    k_row<<<V / 8, 256>>>(out);
}

// round 10
// speedup vs baseline: 1.4290x; 1.4238x over previous
#include <cuda_runtime.h>
#include <cuda_fp16.h>

#define V 8192
#define E 262144
#define D 128
#define SLOTS 128           // hash slots per row (power of 2)
#define GB 256              // gemm grid: 128 row-tiles x 2 col-halves

// ---------------- scratch (device globals; no allocations allowed) ----------
__device__ __half             g_hwh[V * D];      // hw in fp16 (2 MB, L2-resident)
__device__ float              g_s1p[2 * V];      // s1 partials (per col-half)
__device__ float              g_s2p[2 * V];      // s2 partials
__device__ float              g_Spart[GB * 64];  // per-block 64-col colsum partials
__device__ float              g_S[D];            // reduced colsum of hw
__device__ unsigned long long g_ew64[(size_t)V * SLOTS]; // (idx+1)<<29|dst<<16|half(w)
__device__ int                g_is64;            // edge_index dtype flag

// =================== K1: GEMM hw = h @ W^T, 64x64 tiles, grid 256 ============
// Block b: rows rt*64..rt*64+63, cols ch*64..ch*64+63 (rt=b>>1, ch=b&1).
// 256 threads (tx 0..15 -> 4 cols, ty 0..15 -> 4 rows), acc 4x4.
// Epilogue: fp16 hw store, s1/s2 half-partials, 64-col colsum partial.
__global__ void __launch_bounds__(256) k_gemm(const float* __restrict__ h,
                                              const float* __restrict__ Wm,
                                              const float* __restrict__ att,
                                              const int* __restrict__ e32) {
    __shared__ float sh_A[32][68];    // [k][row], 16B-aligned rows
    __shared__ float sh_B[32][68];    // [k][col]
    __shared__ float s1s[64], s2s[64], cs[64];

    int tid = threadIdx.x;
    int tx = tid & 15, ty = tid >> 4;
    int b = blockIdx.x, rt = b >> 1, ch = b & 1;
    int row0 = rt * 64, col0 = ch * 64;

    // int64/int32 detection (block 0): int64 values < 2^13 => odd words all 0
    if (b == 0) {
        __shared__ int flag;
        if (tid == 0) flag = 0;
        __syncthreads();
        if (e32[2 * tid + 1] != 0) atomicExch(&flag, 1);
        __syncthreads();
        if (tid == 0) g_is64 = (flag == 0) ? 1 : 0;
    }

    if (tid < 64) { s1s[tid] = 0.f; s2s[tid] = 0.f; cs[tid] = 0.f; }

    float acc[4][4];
#pragma unroll
    for (int r = 0; r < 4; r++)
#pragma unroll
        for (int c = 0; c < 4; c++) acc[r][c] = 0.f;

    for (int k0 = 0; k0 < 128; k0 += 32) {
        __syncthreads();
        // A: 64 rows x 32 k = 512 float4, 2 per thread
#pragma unroll
        for (int i = 0; i < 2; i++) {
            int idx = tid + i * 256;
            int row = idx >> 3, q = idx & 7;
            float4 v = *(const float4*)(h + (size_t)(row0 + row) * D + k0 + q * 4);
            sh_A[q * 4 + 0][row] = v.x;
            sh_A[q * 4 + 1][row] = v.y;
            sh_A[q * 4 + 2][row] = v.z;
            sh_A[q * 4 + 3][row] = v.w;
        }
        // B: 64 cols x 32 k = 512 float4, 2 per thread (W row-major [col][k])
#pragma unroll
        for (int i = 0; i < 2; i++) {
            int idx = tid + i * 256;
            int col = idx >> 3, q = idx & 7;
            float4 v = *(const float4*)(Wm + (size_t)(col0 + col) * D + k0 + q * 4);
            sh_B[q * 4 + 0][col] = v.x;
            sh_B[q * 4 + 1][col] = v.y;
            sh_B[q * 4 + 2][col] = v.z;
            sh_B[q * 4 + 3][col] = v.w;
        }
        __syncthreads();
#pragma unroll
        for (int k = 0; k < 32; k++) {
            float4 av = *(const float4*)&sh_A[k][ty * 4];   // LDS.128 (broadcast x16)
            float4 bv = *(const float4*)&sh_B[k][tx * 4];   // LDS.128 conflict-free
            float ar[4] = {av.x, av.y, av.z, av.w};
            float br[4] = {bv.x, bv.y, bv.z, bv.w};
#pragma unroll
            for (int r = 0; r < 4; r++)
#pragma unroll
                for (int c = 0; c < 4; c++) acc[r][c] += ar[r] * br[c];
        }
    }

    // ---- epilogue ----
    // fp16 store: 4 rows x 8B (4 halves) per thread
#pragma unroll
    for (int r = 0; r < 4; r++) {
        int row = row0 + ty * 4 + r;
        __half2 q0 = __floats2half2_rn(acc[r][0], acc[r][1]);
        __half2 q1 = __floats2half2_rn(acc[r][2], acc[r][3]);
        uint2 u;
        u.x = *(unsigned*)&q0; u.y = *(unsigned*)&q1;
        *(uint2*)(g_hwh + (size_t)row * D + col0 + tx * 4) = u;
    }

    // s1/s2 partials over this block's 64 cols
    float4 a1 = *(const float4*)(att + col0 + tx * 4);
    float4 a2 = *(const float4*)(att + D + col0 + tx * 4);
    float a1v[4] = {a1.x, a1.y, a1.z, a1.w};
    float a2v[4] = {a2.x, a2.y, a2.z, a2.w};
#pragma unroll
    for (int r = 0; r < 4; r++) {
        float p1 = 0.f, p2 = 0.f;
#pragma unroll
        for (int c = 0; c < 4; c++) { p1 += acc[r][c] * a1v[c]; p2 += acc[r][c] * a2v[c]; }
        atomicAdd(&s1s[ty * 4 + r], p1);
        atomicAdd(&s2s[ty * 4 + r], p2);
    }
    // colsum partial
#pragma unroll
    for (int c = 0; c < 4; c++)
        atomicAdd(&cs[tx * 4 + c], acc[0][c] + acc[1][c] + acc[2][c] + acc[3][c]);
    __syncthreads();
    if (tid < 64) {
        g_s1p[ch * V + row0 + tid] = s1s[tid];
        g_s2p[ch * V + row0 + tid] = s2s[tid];
        g_Spart[b * 64 + tid] = cs[tid];
    }
}

// =================== K2: per-edge logit + hash insert (dedup by atomicMax) ===
// Record: bits[0:16)=half(w), [16:29)=dst, [29:48)=edge_idx+1  (max idx wins)
__global__ void k_scatter(const int* __restrict__ e32) {
    // block 0: reduce colsum partials -> g_S (k_row reads it later)
    if (blockIdx.x == 0 && threadIdx.x < D) {
        int half = threadIdx.x >> 6, cl = threadIdx.x & 63;
        float s = 0.f;
#pragma unroll 8
        for (int rt = 0; rt < 128; rt++) s += g_Spart[(rt * 2 + half) * 64 + cl];
        g_S[threadIdx.x] = s;
    }
    int e = blockIdx.x * blockDim.x + threadIdx.x;
    if (e >= E) return;
    int src, dst;
    if (g_is64) {
        src = ((const int2*)e32)[e].x;
        dst = ((const int2*)e32)[E + e].x;
    } else {
        src = e32[e];
        dst = e32[E + e];
    }
    float a = (g_s1p[src] + g_s1p[V + src]) + (g_s2p[dst] + g_s2p[V + dst]);
    a = a > 0.f ? a : 0.2f * a;                       // LeakyReLU(0.2)
    float w = expm1f(a);                              // exp(a) - 1
    unsigned wh = (unsigned)__half_as_ushort(__float2half_rn(w));
    unsigned long long rec = ((unsigned long long)(unsigned)(e + 1) << 29)
                           | ((unsigned long long)(unsigned)dst << 16) | wh;
    unsigned slot = ((unsigned)dst * 2654435761u) >> 25;   // 7-bit hash
    unsigned long long* tab = g_ew64 + (size_t)src * SLOTS;
    for (int probe = 0; probe < SLOTS; probe++) {
        unsigned long long old = atomicCAS(&tab[slot], 0ULL, rec);
        if (old == 0ULL) break;                            // claimed empty slot
        if (((unsigned)(old >> 16) & 0x1FFFu) == (unsigned)dst) {
            atomicMax(&tab[slot], rec);                    // last-write-wins
            break;
        }
        slot = (slot + 1) & (SLOTS - 1);
    }
}

// =================== K3: slot scan + compact + gather + normalize ============
__global__ void __launch_bounds__(256, 5) k_row(float* __restrict__ out) {
    __shared__ uint2 sm[8][SLOTS];     // {dst, float bits of w}
    int wid = threadIdx.x >> 5, lane = threadIdx.x & 31;
    int row = blockIdx.x * 8 + wid;
    unsigned long long* tab = g_ew64 + (size_t)row * SLOTS;

    float dsum = 0.f;
    int cnt = 0;
#pragma unroll
    for (int rnd = 0; rnd < SLOTS / 32; rnd++) {
        int s = rnd * 32 + lane;
        unsigned long long v = tab[s];
        tab[s] = 0ULL;                                   // replay-safe re-zero
        unsigned mask = __ballot_sync(0xffffffffu, v != 0ULL);
        if (v != 0ULL) {
            int pos = cnt + __popc(mask & ((1u << lane) - 1u));
            float w = __half2float(__ushort_as_half((unsigned short)(v & 0xFFFFu)));
            sm[wid][pos] = make_uint2((unsigned)(v >> 16) & 0x1FFFu,
                                      __float_as_uint(w));
            dsum += w;
        }
        cnt += __popc(mask);
    }
    int dpad = (cnt + 7) & ~7;
    for (int t = cnt + lane; t < dpad; t += 32)
        sm[wid][t] = make_uint2(0u, 0u);                 // harmless pad (w=0)
    __syncwarp();

    // pair-gather: lanes 0-15 edge A, 16-31 edge B; 16B (8 halves) per lane
    float acc[8];
#pragma unroll
    for (int i = 0; i < 8; i++) acc[i] = 0.f;
    int half_ = lane >> 4;
    int cl = (lane & 15) * 8;
    const __half* hw = g_hwh;

    for (int t = 0; t < dpad; t += 8) {
#pragma unroll
        for (int p = 0; p < 4; p++) {
            uint2 m = sm[wid][t + 2 * p + half_];
            float w = __uint_as_float(m.y);
            uint4 v = *(const uint4*)(hw + (size_t)m.x * D + cl);
            float2 f0 = __half22float2(*(__half2*)&v.x);
            float2 f1 = __half22float2(*(__half2*)&v.y);
            float2 f2 = __half22float2(*(__half2*)&v.z);
            float2 f3 = __half22float2(*(__half2*)&v.w);
            acc[0] += w * f0.x; acc[1] += w * f0.y;
            acc[2] += w * f1.x; acc[3] += w * f1.y;
            acc[4] += w * f2.x; acc[5] += w * f2.y;
            acc[6] += w * f3.x; acc[7] += w * f3.y;
        }
    }

#pragma unroll
    for (int i = 0; i < 8; i++) acc[i] += __shfl_xor_sync(0xffffffffu, acc[i], 16);
#pragma unroll
    for (int o = 16; o; o >>= 1) dsum += __shfl_xor_sync(0xffffffffu, dsum, o);

    float inv = 1.f / ((float)V + dsum);
    if (lane < 16) {
        float4 Sa = *(const float4*)(g_S + cl);
        float4 Sb = *(const float4*)(g_S + cl + 4);
        float4 o0, o1;
        o0.x = (Sa.x + acc[0]) * inv; o0.y = (Sa.y + acc[1]) * inv;
        o0.z = (Sa.z + acc[2]) * inv; o0.w = (Sa.w + acc[3]) * inv;
        o1.x = (Sb.x + acc[4]) * inv; o1.y = (Sb.y + acc[5]) * inv;
        o1.z = (Sb.z + acc[6]) * inv; o1.w = (Sb.w + acc[7]) * inv;
        *(float4*)(out + (size_t)row * D + cl) = o0;
        *(float4*)(out + (size_t)row * D + cl + 4) = o1;
    }
}

// ----------------------------------------------------------------------------
extern "C" void kernel_launch(void* const* d_in, const int* in_sizes, int n_in,
                              void* d_out, int out_size) {
    const float* h   = (const float*)d_in[0];
    const int*   ei  = (const int*)d_in[1];
    const float* Wm  = (const float*)d_in[2];
    const float* att = (const float*)d_in[3];
    float* out = (float*)d_out;

    k_gemm<<<GB, 256>>>(h, Wm, att, ei);
    k_scatter<<<E / 256, 256>>>(ei);
    k_row<<<V / 8, 256>>>(out);
}